// round 16
// baseline (speedup 1.0000x reference)
#include <cuda_runtime.h>
#include <cuda_fp16.h>
#include <cuda_bf16.h>

#define NN 50000
#define EE 800000
#define HH 128
#define GG 500
#define FC1 64
#define EPSBN 1e-5f
#define AGG_NB 6250      /* 50000/8 */
#define STAT_NB 128
#define ROWS_PER_STAT 49 /* 128*49 = 6272 >= 6250 */
#define SCAN_TB 256
#define SCAN_NB 196      /* 196*256 = 50176 >= NN */

// ---------------- device scratch (static, no allocation) ----------------
__device__ __align__(16) unsigned g_h16u[NN * (HH / 2)];  // fp16 messages
__device__ float g_agg[NN * HH];
__device__ int   g_cnt[NN];
__device__ int   g_fill[NN];
__device__ int   g_ptr[NN + 1];
__device__ float g_dis[NN];
__device__ int   g_csr_s[EE];    // CSR: src only (weights computed in agg)
__device__ int   g_bsum[SCAN_NB];
__device__ int   g_boff[SCAN_NB];
__device__ float g_ps1[AGG_NB * HH];
__device__ float g_pq1[AGG_NB * HH];
__device__ float g_mids[STAT_NB * HH];
__device__ float g_midq[STAT_NB * HH];
__device__ float g_bn_a[HH];
__device__ float g_bn_b[HH];
__device__ int   g_goff[GG + 1];
__device__ float g_z[GG * FC1];
// W pre-split to bf16 hi/lo, transposed & packed: [layer][n][k/2] (k-pairs)
__device__ __align__(16) unsigned g_wt2h[3][HH * (HH / 2)];
__device__ __align__(16) unsigned g_wt2l[3][HH * (HH / 2)];
__device__ int   g_tick;      // scanall ticket
__device__ int   g_flag;      // scanall release flag
__device__ int   g_stick[3];  // stats tickets (per stats slot)
__device__ int   g_sflag[3];  // stats release flags
__device__ int   g_tickP;     // poolhead head ticket
__device__ int   g_is64;

// ---------------- helpers ----------------
__device__ __forceinline__ int ld_idx(const void* p, long long i, int is64) {
    return is64 ? (int)(((const long long*)p)[i]) : ((const int*)p)[i];
}

// bf16 hi/lo split of two floats, packed into bf16x2 words (low = first elem)
__device__ __forceinline__ unsigned packsplit(float v0, float v1, unsigned* plo) {
    __nv_bfloat16 h0 = __float2bfloat16(v0);
    __nv_bfloat16 h1 = __float2bfloat16(v1);
    float l0f = v0 - __bfloat162float(h0);
    float l1f = v1 - __bfloat162float(h1);
    __nv_bfloat16 l0 = __float2bfloat16(l0f);
    __nv_bfloat16 l1 = __float2bfloat16(l1f);
    *plo = ((unsigned)__bfloat16_as_ushort(l1) << 16) | __bfloat16_as_ushort(l0);
    return ((unsigned)__bfloat16_as_ushort(h1) << 16) | __bfloat16_as_ushort(h0);
}

// ---------------- pre1: zero + counters + dtype detect + W presplit --------
__global__ void k_pre1(const void* eidx, const float* W1, const float* W2,
                       const float* W3) {
    int i = blockIdx.x * blockDim.x + threadIdx.x;
    if (i < NN) { g_cnt[i] = 0; g_fill[i] = 0; }
    if (i == 0) {
        g_tick = 0; g_flag = 0; g_tickP = 0;
        for (int l = 0; l < 3; l++) { g_stick[l] = 0; g_sflag[l] = 0; }
    }
    if (blockIdx.x == 0) {
        __shared__ int any;
        if (threadIdx.x == 0) any = 0;
        __syncthreads();
        if (((const int*)eidx)[2 * threadIdx.x + 1] != 0) atomicOr(&any, 1);
        __syncthreads();
        if (threadIdx.x == 0) g_is64 = any ? 0 : 1;
    }
    // W bf16 hi/lo presplit, transposed to [n][k/2]: 3 * 128 * 64 pairs
    if (i < 3 * HH * (HH / 2)) {
        int l = i / (HH * (HH / 2));
        int j = i - l * (HH * (HH / 2));
        int n = j >> 6;
        int kk = j & 63;
        const float* Wsrc = (l == 0) ? W1 : (l == 1) ? W2 : W3;
        float w0 = Wsrc[(2 * kk) * HH + n];
        float w1 = Wsrc[(2 * kk + 1) * HH + n];
        unsigned lo;
        unsigned hi = packsplit(w0, w1, &lo);
        g_wt2h[l][n * 64 + kk] = hi;
        g_wt2l[l][n * 64 + kk] = lo;
    }
}

// ---------------- count (edge histogram) + graph bounds ----------------
__global__ void k_count(const void* eidx, const void* batch) {
    int e = blockIdx.x * blockDim.x + threadIdx.x;
    int is64 = g_is64;
    if (e < EE) {
        int d = ld_idx(eidx, (long long)EE + e, is64);
        atomicAdd(&g_cnt[d], 1);
    }
    if (e < NN) {
        int b = ld_idx(batch, e, is64);
        int bn = (e + 1 < NN) ? ld_idx(batch, e + 1, is64) : GG;
        if (e == 0)
            for (int g = 0; g <= b && g <= GG; g++) g_goff[g] = 0;
        int hi = bn < GG ? bn : GG;
        for (int g = b + 1; g <= hi; g++) g_goff[g] = e + 1;
    }
}

// ---------------- single-launch CSR scan (ticket + flag spin) ----------------
__global__ void __launch_bounds__(SCAN_TB) k_scanall() {
    __shared__ int sm[SCAN_TB];
    __shared__ int islast;
    int t = threadIdx.x;
    int b = blockIdx.x;
    int i = b * SCAN_TB + t;
    int c = (i < NN) ? g_cnt[i] : 0;
    sm[t] = c;
    __syncthreads();
    for (int off = 1; off < SCAN_TB; off <<= 1) {
        int v = (t >= off) ? sm[t - off] : 0;
        __syncthreads();
        sm[t] += v;
        __syncthreads();
    }
    int local_ex = sm[t] - c;
    int total = sm[SCAN_TB - 1];
    if (t == 0) {
        g_bsum[b] = total;
        __threadfence();
        islast = (atomicAdd(&g_tick, 1) == SCAN_NB - 1);
    }
    __syncthreads();
    if (islast) {
        int v = (t < SCAN_NB) ? g_bsum[t] : 0;
        __syncthreads();
        sm[t] = v;
        __syncthreads();
        for (int off = 1; off < SCAN_TB; off <<= 1) {
            int u = (t >= off) ? sm[t - off] : 0;
            __syncthreads();
            sm[t] += u;
            __syncthreads();
        }
        if (t < SCAN_NB) g_boff[t] = sm[t] - v;
        __threadfence();
        __syncthreads();
        if (t == 0) atomicExch(&g_flag, 1);
    }
    if (t == 0) {
        while (atomicAdd(&g_flag, 0) == 0) __nanosleep(100);
    }
    __syncthreads();
    __threadfence();
    int ex = local_ex + g_boff[b];
    if (i < NN) {
        g_ptr[i] = ex;
        g_dis[i] = rsqrtf((float)(c + 1));
        if (i == NN - 1) g_ptr[NN] = ex + c;
    }
}

// ---------------- CSR fill: src index only (no dis gathers) ----------------
__global__ void k_fill(const void* eidx) {
    int e = blockIdx.x * blockDim.x + threadIdx.x;
    if (e >= EE) return;
    int is64 = g_is64;
    int s = ld_idx(eidx, e, is64);
    int d = ld_idx(eidx, (long long)EE + e, is64);
    int pos = atomicAdd(&g_fill[d], 1);
    g_csr_s[g_ptr[d] + pos] = s;
}

// ------- persistent 3xBF16 GEMM: W resident, double-buffered X prefetch ----
// Optional fused BN-stats finalize stage (slot `which`) before the mainloop.
#define P_STRIDE 68    /* 64 bf16x2 pairs + pad (uints) */
#define XBUF (2 * 128 * P_STRIDE)
#define GEMM_SMEM ((2 * 128 * P_STRIDE + 2 * XBUF) * 4)   /* ~209 KB */
#define GEMM_TILES ((NN + 127) / 128)
#define GEMM_BLK 148

template <bool BN>
__global__ void __launch_bounds__(512, 1) k_gemm_tc(const float* __restrict__ X,
                                                    const unsigned* __restrict__ Wth,
                                                    const unsigned* __restrict__ Wtl,
                                                    const float* __restrict__ gam,
                                                    const float* __restrict__ bet,
                                                    int which) {
    extern __shared__ unsigned usmem[];
    unsigned* Wh2 = usmem;                      // [128][68]
    unsigned* Wl2 = Wh2 + 128 * P_STRIDE;
    unsigned* Xb  = Wl2 + 128 * P_STRIDE;       // [2][2][128*68]
    int tid = threadIdx.x;
    int b = blockIdx.x;

    // ---- fused BN stats (slot which): blocks 0..127 reduce; last finalizes
    if (BN) {
        if (b < STAT_NB) {
            __shared__ int islast;
            if (tid < 256) {
                int c = tid & (HH - 1);
                int isq = tid >> 7;
                const float* src = isq ? g_pq1 : g_ps1;
                float s = 0.f;
                int r0 = b * ROWS_PER_STAT;
                int r1 = r0 + ROWS_PER_STAT;
                if (r1 > AGG_NB) r1 = AGG_NB;
                for (int r = r0; r < r1; r++) s += src[r * HH + c];
                if (isq) g_midq[b * HH + c] = s;
                else     g_mids[b * HH + c] = s;
            }
            __syncthreads();
            if (tid == 0) {
                __threadfence();
                islast = (atomicAdd(&g_stick[which], 1) == STAT_NB - 1);
            }
            __syncthreads();
            if (islast) {
                __threadfence();
                if (tid < HH) {
                    float su = 0.f, q = 0.f;
                    for (int b2 = 0; b2 < STAT_NB; b2++) {
                        su += g_mids[b2 * HH + tid];
                        q  += g_midq[b2 * HH + tid];
                    }
                    float m = su / (float)NN;
                    float var = q / (float)NN - m * m;
                    float a = gam[tid] * rsqrtf(var + EPSBN);
                    g_bn_a[tid] = a;
                    g_bn_b[tid] = bet[tid] - m * a;
                }
                __syncthreads();
                if (tid == 0) {
                    __threadfence();
                    atomicExch(&g_sflag[which], 1);
                }
            }
        }
    }

    int wid = tid >> 5;
    int lane = tid & 31;
    int mwid = wid >> 2;
    int nwid = wid & 3;
    int g = lane >> 2;
    int tg = lane & 3;
    int lr[8], lc4[8];
#pragma unroll
    for (int i = 0; i < 8; i++) {
        int q = i * 512 + tid;
        lr[i] = q >> 5;
        lc4[i] = q & 31;
    }

    // W resident load (once; independent of stats -> overlaps the wait)
#pragma unroll
    for (int i = 0; i < 4; i++) {
        int q = i * 512 + tid;
        int r = q >> 4;
        int c = (q & 15) * 4;
        *(uint4*)(Wh2 + r * P_STRIDE + c) = *(const uint4*)(Wth + r * 64 + c);
        *(uint4*)(Wl2 + r * P_STRIDE + c) = *(const uint4*)(Wtl + r * 64 + c);
    }

    // all blocks wait for bn_a/bn_b (all 148 resident -> spin safe)
    if (BN) {
        if (tid == 0) {
            while (atomicAdd(&g_sflag[which], 0) == 0) __nanosleep(64);
        }
        __syncthreads();
        __threadfence();
    }

#define LOADX(TILE, PF)                                                     \
    do {                                                                    \
        int row0p = (TILE) * 128;                                           \
        _Pragma("unroll") for (int i = 0; i < 8; i++) {                     \
            int gr = row0p + lr[i];                                         \
            PF[i] = make_float4(0.f, 0.f, 0.f, 0.f);                        \
            if (gr < NN) PF[i] = *(const float4*)(X + (size_t)gr * 128 + lc4[i] * 4); \
        }                                                                   \
    } while (0)

#define STOREX(BUF, PF)                                                     \
    do {                                                                    \
        _Pragma("unroll") for (int i = 0; i < 8; i++) {                     \
            float4 v = PF[i];                                               \
            if (BN) {                                                       \
                int ch = lc4[i] * 4;                                        \
                v.x = fmaxf(g_bn_a[ch + 0] * v.x + g_bn_b[ch + 0], 0.f);    \
                v.y = fmaxf(g_bn_a[ch + 1] * v.y + g_bn_b[ch + 1], 0.f);    \
                v.z = fmaxf(g_bn_a[ch + 2] * v.z + g_bn_b[ch + 2], 0.f);    \
                v.w = fmaxf(g_bn_a[ch + 3] * v.w + g_bn_b[ch + 3], 0.f);    \
            }                                                               \
            unsigned lo0, lo1;                                              \
            unsigned hi0 = packsplit(v.x, v.y, &lo0);                       \
            unsigned hi1 = packsplit(v.z, v.w, &lo1);                       \
            int o = lr[i] * P_STRIDE + lc4[i] * 2;                          \
            (BUF)[o] = hi0; (BUF)[o + 1] = hi1;                             \
            (BUF)[o + 128 * P_STRIDE] = lo0;                                \
            (BUF)[o + 128 * P_STRIDE + 1] = lo1;                            \
        }                                                                   \
    } while (0)

#define MMA16(A0, A1, A2, A3, B0, B1, C)                                \
    asm volatile(                                                       \
        "mma.sync.aligned.m16n8k16.row.col.f32.bf16.bf16.f32 "          \
        "{%0,%1,%2,%3}, {%4,%5,%6,%7}, {%8,%9}, {%0,%1,%2,%3};"         \
        : "+f"(C[0]), "+f"(C[1]), "+f"(C[2]), "+f"(C[3])                \
        : "r"(A0), "r"(A1), "r"(A2), "r"(A3), "r"(B0), "r"(B1))

    // prologue: tile b into buf 0
    {
        float4 pf[8];
        LOADX(b, pf);
        STOREX(Xb, pf);
    }
    __syncthreads();

    int nt = 0;
    for (int tile = b; tile < GEMM_TILES; tile += GEMM_BLK, nt++) {
        int cur = nt & 1;
        unsigned* Xh2 = Xb + cur * XBUF;
        unsigned* Xl2 = Xh2 + 128 * P_STRIDE;
        int row0 = tile * 128;
        int next = tile + GEMM_BLK;

        float4 pf[8];
        if (next < GEMM_TILES) LOADX(next, pf);

        float acc[2][4][4];
#pragma unroll
        for (int mi = 0; mi < 2; mi++)
#pragma unroll
            for (int ni = 0; ni < 4; ni++)
#pragma unroll
                for (int j = 0; j < 4; j++) acc[mi][ni][j] = 0.f;

#pragma unroll
        for (int kp = 0; kp < 64; kp += 8) {
            unsigned ah[2][4], al[2][4];
#pragma unroll
            for (int mi = 0; mi < 2; mi++) {
                int rb = mwid * 32 + mi * 16;
                int o0 = (rb + g) * P_STRIDE + kp + tg;
                int o1 = (rb + g + 8) * P_STRIDE + kp + tg;
                ah[mi][0] = Xh2[o0];
                ah[mi][1] = Xh2[o1];
                ah[mi][2] = Xh2[o0 + 4];
                ah[mi][3] = Xh2[o1 + 4];
                al[mi][0] = Xl2[o0];
                al[mi][1] = Xl2[o1];
                al[mi][2] = Xl2[o0 + 4];
                al[mi][3] = Xl2[o1 + 4];
            }
#pragma unroll
            for (int ni = 0; ni < 4; ni++) {
                int cb = nwid * 32 + ni * 8;
                int o = (cb + g) * P_STRIDE + kp + tg;
                unsigned bh0 = Wh2[o];
                unsigned bh1 = Wh2[o + 4];
                unsigned bl0 = Wl2[o];
                unsigned bl1 = Wl2[o + 4];
#pragma unroll
                for (int mi = 0; mi < 2; mi++) {
                    MMA16(ah[mi][0], ah[mi][1], ah[mi][2], ah[mi][3],
                          bh0, bh1, acc[mi][ni]);
                    MMA16(ah[mi][0], ah[mi][1], ah[mi][2], ah[mi][3],
                          bl0, bl1, acc[mi][ni]);
                    MMA16(al[mi][0], al[mi][1], al[mi][2], al[mi][3],
                          bh0, bh1, acc[mi][ni]);
                }
            }
        }

        if (next < GEMM_TILES) STOREX(Xb + (cur ^ 1) * XBUF, pf);

        // epilogue: fp16 pairs
#pragma unroll
        for (int mi = 0; mi < 2; mi++) {
#pragma unroll
            for (int ni = 0; ni < 4; ni++) {
                int col = nwid * 32 + ni * 8 + tg * 2;
                int r1 = row0 + mwid * 32 + mi * 16 + g;
                int r2 = r1 + 8;
                if (r1 < NN) {
                    __half2 h = __floats2half2_rn(acc[mi][ni][0], acc[mi][ni][1]);
                    g_h16u[(size_t)r1 * 64 + (col >> 1)] = *(unsigned*)&h;
                }
                if (r2 < NN) {
                    __half2 h = __floats2half2_rn(acc[mi][ni][2], acc[mi][ni][3]);
                    g_h16u[(size_t)r2 * 64 + (col >> 1)] = *(unsigned*)&h;
                }
            }
        }
        __syncthreads();
    }
#undef MMA16
#undef LOADX
#undef STOREX
}

// ---------------- aggregation (fp16 gather, on-the-fly weights) ------------
__global__ void __launch_bounds__(256) k_agg(const float* __restrict__ bias) {
    __shared__ float ps[8][HH];
    __shared__ float pq[8][HH];
    int w = threadIdx.x >> 5;
    int lane = threadIdx.x & 31;
    int d = blockIdx.x * 8 + w;   // NN = 6250*8 exact

    const uint2* Hv = (const uint2*)g_h16u;
    float sd = g_dis[d];
    float ws = sd * sd;
    uint2 u = Hv[(size_t)d * 32 + lane];
    float2 f0 = __half22float2(*(__half2*)&u.x);
    float2 f1 = __half22float2(*(__half2*)&u.y);
    float4 acc = make_float4(f0.x * ws, f0.y * ws, f1.x * ws, f1.y * ws);

    int beg = g_ptr[d], end = g_ptr[d + 1];
    int j = beg;
    for (; j + 4 <= end; j += 4) {
        int s0 = g_csr_s[j + 0], s1 = g_csr_s[j + 1];
        int s2 = g_csr_s[j + 2], s3 = g_csr_s[j + 3];
        float w0 = __ldg(&g_dis[s0]) * sd;
        float w1 = __ldg(&g_dis[s1]) * sd;
        float w2 = __ldg(&g_dis[s2]) * sd;
        float w3 = __ldg(&g_dis[s3]) * sd;
        uint2 u0 = Hv[(size_t)s0 * 32 + lane];
        uint2 u1 = Hv[(size_t)s1 * 32 + lane];
        uint2 u2 = Hv[(size_t)s2 * 32 + lane];
        uint2 u3 = Hv[(size_t)s3 * 32 + lane];
        float2 a0, c0;
        a0 = __half22float2(*(__half2*)&u0.x); c0 = __half22float2(*(__half2*)&u0.y);
        acc.x += a0.x * w0; acc.y += a0.y * w0; acc.z += c0.x * w0; acc.w += c0.y * w0;
        a0 = __half22float2(*(__half2*)&u1.x); c0 = __half22float2(*(__half2*)&u1.y);
        acc.x += a0.x * w1; acc.y += a0.y * w1; acc.z += c0.x * w1; acc.w += c0.y * w1;
        a0 = __half22float2(*(__half2*)&u2.x); c0 = __half22float2(*(__half2*)&u2.y);
        acc.x += a0.x * w2; acc.y += a0.y * w2; acc.z += c0.x * w2; acc.w += c0.y * w2;
        a0 = __half22float2(*(__half2*)&u3.x); c0 = __half22float2(*(__half2*)&u3.y);
        acc.x += a0.x * w3; acc.y += a0.y * w3; acc.z += c0.x * w3; acc.w += c0.y * w3;
    }
    for (; j < end; j++) {
        int s = g_csr_s[j];
        float wj = __ldg(&g_dis[s]) * sd;
        uint2 us = Hv[(size_t)s * 32 + lane];
        float2 a0 = __half22float2(*(__half2*)&us.x);
        float2 c0 = __half22float2(*(__half2*)&us.y);
        acc.x += a0.x * wj; acc.y += a0.y * wj; acc.z += c0.x * wj; acc.w += c0.y * wj;
    }
    float4 b4 = ((const float4*)bias)[lane];
    acc.x += b4.x; acc.y += b4.y; acc.z += b4.z; acc.w += b4.w;
    ((float4*)(g_agg + (size_t)d * HH))[lane] = acc;

    int c0i = 4 * lane;
    ps[w][c0i + 0] = acc.x; ps[w][c0i + 1] = acc.y;
    ps[w][c0i + 2] = acc.z; ps[w][c0i + 3] = acc.w;
    pq[w][c0i + 0] = acc.x * acc.x; pq[w][c0i + 1] = acc.y * acc.y;
    pq[w][c0i + 2] = acc.z * acc.z; pq[w][c0i + 3] = acc.w * acc.w;
    __syncthreads();
    int t = threadIdx.x;
    if (t < HH) {
        float s = 0.f;
#pragma unroll
        for (int i = 0; i < 8; i++) s += ps[i][t];
        g_ps1[blockIdx.x * HH + t] = s;
    } else {
        int c = t - HH;
        float s = 0.f;
#pragma unroll
        for (int i = 0; i < 8; i++) s += pq[i][c];
        g_pq1[blockIdx.x * HH + c] = s;
    }
}

// ---- poolhead: fused layer-3 BN stats + pool + FC1 + ticketed head ---------
__global__ void __launch_bounds__(128) k_poolhead(
    const float* __restrict__ gam3, const float* __restrict__ bet3,
    const float* __restrict__ Wf, const float* __restrict__ bf,
    const float* __restrict__ gam, const float* __restrict__ bet,
    const float* __restrict__ W2f, const float* __restrict__ b2f,
    float* __restrict__ out) {
    __shared__ float pooled[HH];
    __shared__ float fa[FC1], fb[FC1];
    __shared__ int s_tk;
    int gI = blockIdx.x;
    int t = threadIdx.x;

    // layer-3 BN stats (slot 2): blocks 0..127 reduce; last finalizes
    if (gI < STAT_NB) {
        __shared__ int islast;
        {
            float s = 0.f, q = 0.f;
            int r0 = gI * ROWS_PER_STAT;
            int r1 = r0 + ROWS_PER_STAT;
            if (r1 > AGG_NB) r1 = AGG_NB;
            for (int r = r0; r < r1; r++) {
                s += g_ps1[r * HH + t];
                q += g_pq1[r * HH + t];
            }
            g_mids[gI * HH + t] = s;
            g_midq[gI * HH + t] = q;
        }
        __syncthreads();
        if (t == 0) {
            __threadfence();
            islast = (atomicAdd(&g_stick[2], 1) == STAT_NB - 1);
        }
        __syncthreads();
        if (islast) {
            __threadfence();
            float su = 0.f, q = 0.f;
            for (int b2 = 0; b2 < STAT_NB; b2++) {
                su += g_mids[b2 * HH + t];
                q  += g_midq[b2 * HH + t];
            }
            float m = su / (float)NN;
            float var = q / (float)NN - m * m;
            float a = gam3[t] * rsqrtf(var + EPSBN);
            g_bn_a[t] = a;
            g_bn_b[t] = bet3[t] - m * a;
            __syncthreads();
            if (t == 0) {
                __threadfence();
                atomicExch(&g_sflag[2], 1);
            }
        }
    }
    // all 500 blocks wait for bn (all resident: 500 x 128thr -> spin safe)
    if (t == 0) {
        while (atomicAdd(&g_sflag[2], 0) == 0) __nanosleep(64);
    }
    __syncthreads();
    __threadfence();

    int beg = g_goff[gI], end = g_goff[gI + 1];
    float a = g_bn_a[t], b = g_bn_b[t];
    float acc = 0.f;
    for (int r = beg; r < end; r++) {
        float v = g_agg[(size_t)r * HH + t];
        acc += fmaxf(a * v + b, 0.f);
    }
    float cnt = (float)(end - beg);
    pooled[t] = acc / fmaxf(cnt, 1.f);
    __syncthreads();
    if (t < FC1) {
        float s = bf[t];
#pragma unroll 8
        for (int k = 0; k < HH; k++) s += pooled[k] * Wf[k * FC1 + t];
        g_z[gI * FC1 + t] = s;
    }
    __syncthreads();
    if (t == 0) {
        __threadfence();
        s_tk = atomicAdd(&g_tickP, 1);
    }
    __syncthreads();
    if (s_tk != GG - 1) return;       // last block runs the head
    __threadfence();
    if (t < FC1) {
        float s = 0.f, q = 0.f;
#pragma unroll 4
        for (int r = 0; r < GG; r++) {
            float v = g_z[r * FC1 + t];
            s += v;
            q += v * v;
        }
        float m = s / (float)GG;
        float var = q / (float)GG - m * m;
        float av = gam[t] * rsqrtf(var + EPSBN);
        fa[t] = av;
        fb[t] = bet[t] - m * av;
    }
    __syncthreads();
    for (int gg = t; gg < GG; gg += 128) {
        float s = b2f[0];
#pragma unroll 8
        for (int c = 0; c < FC1; c++) {
            float v = g_z[gg * FC1 + c];
            v = fmaxf(fa[c] * v + fb[c], 0.f);
            s += v * W2f[c];
        }
        out[gg] = s;
    }
}

// ---------------- launch ----------------
extern "C" void kernel_launch(void* const* d_in, const int* in_sizes, int n_in,
                              void* d_out, int out_size) {
    const float* x    = (const float*)d_in[0];
    const void*  eidx = d_in[1];
    const void*  batc = d_in[2];
    const float* W1 = (const float*)d_in[3];
    const float* b1 = (const float*)d_in[4];
    const float* g1 = (const float*)d_in[5];
    const float* be1 = (const float*)d_in[6];
    const float* W2 = (const float*)d_in[7];
    const float* b2 = (const float*)d_in[8];
    const float* g2 = (const float*)d_in[9];
    const float* be2 = (const float*)d_in[10];
    const float* W3 = (const float*)d_in[11];
    const float* b3 = (const float*)d_in[12];
    const float* g3 = (const float*)d_in[13];
    const float* be3 = (const float*)d_in[14];
    const float* fcW1 = (const float*)d_in[15];
    const float* fcb1 = (const float*)d_in[16];
    const float* fcg1 = (const float*)d_in[17];
    const float* fcbe1 = (const float*)d_in[18];
    const float* fcW2 = (const float*)d_in[19];
    const float* fcb2 = (const float*)d_in[20];
    float* out = (float*)d_out;

    float* pagg = nullptr;
    unsigned *pwth = nullptr, *pwtl = nullptr;
    cudaGetSymbolAddress((void**)&pagg, g_agg);
    cudaGetSymbolAddress((void**)&pwth, g_wt2h);
    cudaGetSymbolAddress((void**)&pwtl, g_wt2l);

    const int TB = 256;
    const int WSZ = HH * (HH / 2);   // uints per layer in g_wt2h/l

    static int init_done = 0;
    static cudaStream_t s2;
    static cudaEvent_t ev1, ev2;
    if (!init_done) {
        cudaFuncSetAttribute(k_gemm_tc<false>,
                             cudaFuncAttributeMaxDynamicSharedMemorySize, GEMM_SMEM);
        cudaFuncSetAttribute(k_gemm_tc<true>,
                             cudaFuncAttributeMaxDynamicSharedMemorySize, GEMM_SMEM);
        cudaStreamCreateWithFlags(&s2, cudaStreamNonBlocking);
        cudaEventCreateWithFlags(&ev1, cudaEventDisableTiming);
        cudaEventCreateWithFlags(&ev2, cudaEventDisableTiming);
        init_done = 1;
    }

    // preprocessing chain; layer-1 GEMM forked onto s2 (needs only pre1 + x)
    k_pre1<<<SCAN_NB, TB>>>(eidx, W1, W2, W3);
    cudaEventRecord(ev1, 0);
    cudaStreamWaitEvent(s2, ev1, 0);
    k_gemm_tc<false><<<GEMM_BLK, 512, GEMM_SMEM, s2>>>(x, pwth, pwtl,
                                                       nullptr, nullptr, 0);
    cudaEventRecord(ev2, s2);

    k_count<<<(EE + TB - 1) / TB, TB>>>(eidx, batc);
    k_scanall<<<SCAN_NB, SCAN_TB>>>();
    k_fill<<<(EE + TB - 1) / TB, TB>>>(eidx);
    cudaStreamWaitEvent(0, ev2, 0);

    // layer 1
    k_agg<<<AGG_NB, TB>>>(b1);
    // layer 2 (stats for layer-1 fused into gemm start, slot 0)
    k_gemm_tc<true><<<GEMM_BLK, 512, GEMM_SMEM>>>(pagg, pwth + WSZ, pwtl + WSZ,
                                                  g1, be1, 0);
    k_agg<<<AGG_NB, TB>>>(b2);
    // layer 3 (stats slot 1)
    k_gemm_tc<true><<<GEMM_BLK, 512, GEMM_SMEM>>>(pagg, pwth + 2 * WSZ,
                                                  pwtl + 2 * WSZ, g2, be2, 1);
    k_agg<<<AGG_NB, TB>>>(b3);

    // pool + fc1 + head with fused layer-3 stats (slot 2)
    k_poolhead<<<GG, 128>>>(g3, be3, fcW1, fcb1, fcg1, fcbe1, fcW2, fcb2, out);
}

// round 17
// speedup vs baseline: 1.0391x; 1.0391x over previous
#include <cuda_runtime.h>
#include <cuda_fp16.h>
#include <cuda_bf16.h>

#define NN 50000
#define EE 800000
#define HH 128
#define GG 500
#define FC1 64
#define EPSBN 1e-5f
#define AGG_NB 6250      /* 50000/8 */
#define STAT_NB 128
#define ROWS_PER_STAT 49 /* 128*49 = 6272 >= 6250 */
#define SCAN_TB 256
#define SCAN_NB 196      /* 196*256 = 50176 >= NN */

// ---------------- device scratch (static, no allocation) ----------------
__device__ __align__(16) unsigned g_h16u[NN * (HH / 2)];  // fp16 messages
__device__ float g_agg[NN * HH];
__device__ int   g_cnt[NN];
__device__ int   g_fill[NN];
__device__ int   g_ptr[NN + 1];
__device__ float g_dis[NN];
__device__ __align__(16) uint2 g_csr[EE];   // packed (src, w)
__device__ int   g_bsum[SCAN_NB];
__device__ int   g_boff[SCAN_NB];
__device__ float g_ps1[AGG_NB * HH];
__device__ float g_pq1[AGG_NB * HH];
__device__ float g_mids[STAT_NB * HH];
__device__ float g_midq[STAT_NB * HH];
__device__ float g_bn_a[HH];
__device__ float g_bn_b[HH];
__device__ int   g_goff[GG + 1];
__device__ float g_z[GG * FC1];
// W pre-split to bf16 hi/lo, transposed & packed: [layer][n][k/2] (k-pairs)
__device__ __align__(16) unsigned g_wt2h[3][HH * (HH / 2)];
__device__ __align__(16) unsigned g_wt2l[3][HH * (HH / 2)];
__device__ int   g_tick;      // scanall ticket
__device__ int   g_flag;      // scanall release flag
__device__ int   g_tick2[3];  // stats tickets (per layer)
__device__ int   g_tickP;     // poolhead ticket
__device__ int   g_is64;

// ---------------- helpers ----------------
__device__ __forceinline__ int ld_idx(const void* p, long long i, int is64) {
    return is64 ? (int)(((const long long*)p)[i]) : ((const int*)p)[i];
}

// bf16 hi/lo split of two floats, packed into bf16x2 words (low = first elem)
__device__ __forceinline__ unsigned packsplit(float v0, float v1, unsigned* plo) {
    __nv_bfloat16 h0 = __float2bfloat16(v0);
    __nv_bfloat16 h1 = __float2bfloat16(v1);
    float l0f = v0 - __bfloat162float(h0);
    float l1f = v1 - __bfloat162float(h1);
    __nv_bfloat16 l0 = __float2bfloat16(l0f);
    __nv_bfloat16 l1 = __float2bfloat16(l1f);
    *plo = ((unsigned)__bfloat16_as_ushort(l1) << 16) | __bfloat16_as_ushort(l0);
    return ((unsigned)__bfloat16_as_ushort(h1) << 16) | __bfloat16_as_ushort(h0);
}

// ---------------- pre1: zero + counters + dtype detect + W presplit --------
__global__ void k_pre1(const void* eidx, const float* W1, const float* W2,
                       const float* W3) {
    int i = blockIdx.x * blockDim.x + threadIdx.x;
    if (i < NN) { g_cnt[i] = 0; g_fill[i] = 0; }
    if (i == 0) {
        g_tick = 0; g_flag = 0; g_tickP = 0;
        g_tick2[0] = 0; g_tick2[1] = 0; g_tick2[2] = 0;
    }
    if (blockIdx.x == 0) {
        __shared__ int any;
        if (threadIdx.x == 0) any = 0;
        __syncthreads();
        if (((const int*)eidx)[2 * threadIdx.x + 1] != 0) atomicOr(&any, 1);
        __syncthreads();
        if (threadIdx.x == 0) g_is64 = any ? 0 : 1;
    }
    // W bf16 hi/lo presplit, transposed to [n][k/2]: 3 * 128 * 64 pairs
    if (i < 3 * HH * (HH / 2)) {
        int l = i / (HH * (HH / 2));
        int j = i - l * (HH * (HH / 2));
        int n = j >> 6;
        int kk = j & 63;
        const float* Wsrc = (l == 0) ? W1 : (l == 1) ? W2 : W3;
        float w0 = Wsrc[(2 * kk) * HH + n];
        float w1 = Wsrc[(2 * kk + 1) * HH + n];
        unsigned lo;
        unsigned hi = packsplit(w0, w1, &lo);
        g_wt2h[l][n * 64 + kk] = hi;
        g_wt2l[l][n * 64 + kk] = lo;
    }
}

// ---------------- count (edge histogram) + graph bounds ----------------
__global__ void k_count(const void* eidx, const void* batch) {
    int e = blockIdx.x * blockDim.x + threadIdx.x;
    int is64 = g_is64;
    if (e < EE) {
        int d = ld_idx(eidx, (long long)EE + e, is64);
        atomicAdd(&g_cnt[d], 1);
    }
    if (e < NN) {
        int b = ld_idx(batch, e, is64);
        int bn = (e + 1 < NN) ? ld_idx(batch, e + 1, is64) : GG;
        if (e == 0)
            for (int g = 0; g <= b && g <= GG; g++) g_goff[g] = 0;
        int hi = bn < GG ? bn : GG;
        for (int g = b + 1; g <= hi; g++) g_goff[g] = e + 1;
    }
}

// ---------------- single-launch CSR scan (ticket + flag spin) ----------------
__global__ void __launch_bounds__(SCAN_TB) k_scanall() {
    __shared__ int sm[SCAN_TB];
    __shared__ int islast;
    int t = threadIdx.x;
    int b = blockIdx.x;
    int i = b * SCAN_TB + t;
    int c = (i < NN) ? g_cnt[i] : 0;
    sm[t] = c;
    __syncthreads();
    for (int off = 1; off < SCAN_TB; off <<= 1) {
        int v = (t >= off) ? sm[t - off] : 0;
        __syncthreads();
        sm[t] += v;
        __syncthreads();
    }
    int local_ex = sm[t] - c;
    int total = sm[SCAN_TB - 1];
    if (t == 0) {
        g_bsum[b] = total;
        __threadfence();
        islast = (atomicAdd(&g_tick, 1) == SCAN_NB - 1);
    }
    __syncthreads();
    if (islast) {
        int v = (t < SCAN_NB) ? g_bsum[t] : 0;
        __syncthreads();
        sm[t] = v;
        __syncthreads();
        for (int off = 1; off < SCAN_TB; off <<= 1) {
            int u = (t >= off) ? sm[t - off] : 0;
            __syncthreads();
            sm[t] += u;
            __syncthreads();
        }
        if (t < SCAN_NB) g_boff[t] = sm[t] - v;
        __threadfence();
        __syncthreads();
        if (t == 0) atomicExch(&g_flag, 1);
    }
    if (t == 0) {
        while (atomicAdd(&g_flag, 0) == 0) __nanosleep(100);
    }
    __syncthreads();
    __threadfence();
    int ex = local_ex + g_boff[b];
    if (i < NN) {
        g_ptr[i] = ex;
        g_dis[i] = rsqrtf((float)(c + 1));
        if (i == NN - 1) g_ptr[NN] = ex + c;
    }
}

__global__ void k_fill(const void* eidx) {
    int e = blockIdx.x * blockDim.x + threadIdx.x;
    if (e >= EE) return;
    int is64 = g_is64;
    int s = ld_idx(eidx, e, is64);
    int d = ld_idx(eidx, (long long)EE + e, is64);
    int pos = atomicAdd(&g_fill[d], 1);
    float w = g_dis[s] * g_dis[d];
    g_csr[g_ptr[d] + pos] = make_uint2((unsigned)s, __float_as_uint(w));
}

// ------- persistent 3xBF16 GEMM: W resident, double-buffered X prefetch ----
#define P_STRIDE 68    /* 64 bf16x2 pairs + pad (uints) */
#define XBUF (2 * 128 * P_STRIDE)
#define GEMM_SMEM ((2 * 128 * P_STRIDE + 2 * XBUF) * 4)   /* ~209 KB */
#define GEMM_TILES ((NN + 127) / 128)
#define GEMM_BLK 148

template <bool BN>
__global__ void __launch_bounds__(512, 1) k_gemm_tc(const float* __restrict__ X,
                                                    const unsigned* __restrict__ Wth,
                                                    const unsigned* __restrict__ Wtl) {
    extern __shared__ unsigned usmem[];
    unsigned* Wh2 = usmem;                      // [128][68]
    unsigned* Wl2 = Wh2 + 128 * P_STRIDE;
    unsigned* Xb  = Wl2 + 128 * P_STRIDE;       // [2][2][128*68]
    int tid = threadIdx.x;
    int b = blockIdx.x;

    int wid = tid >> 5;
    int lane = tid & 31;
    int mwid = wid >> 2;
    int nwid = wid & 3;
    int g = lane >> 2;
    int tg = lane & 3;
    int lr[8], lc4[8];
#pragma unroll
    for (int i = 0; i < 8; i++) {
        int q = i * 512 + tid;
        lr[i] = q >> 5;
        lc4[i] = q & 31;
    }

    // W resident load (once)
#pragma unroll
    for (int i = 0; i < 4; i++) {
        int q = i * 512 + tid;
        int r = q >> 4;
        int c = (q & 15) * 4;
        *(uint4*)(Wh2 + r * P_STRIDE + c) = *(const uint4*)(Wth + r * 64 + c);
        *(uint4*)(Wl2 + r * P_STRIDE + c) = *(const uint4*)(Wtl + r * 64 + c);
    }

#define LOADX(TILE, PF)                                                     \
    do {                                                                    \
        int row0p = (TILE) * 128;                                           \
        _Pragma("unroll") for (int i = 0; i < 8; i++) {                     \
            int gr = row0p + lr[i];                                         \
            PF[i] = make_float4(0.f, 0.f, 0.f, 0.f);                        \
            if (gr < NN) PF[i] = *(const float4*)(X + (size_t)gr * 128 + lc4[i] * 4); \
        }                                                                   \
    } while (0)

#define STOREX(BUF, PF)                                                     \
    do {                                                                    \
        _Pragma("unroll") for (int i = 0; i < 8; i++) {                     \
            float4 v = PF[i];                                               \
            if (BN) {                                                       \
                int ch = lc4[i] * 4;                                        \
                v.x = fmaxf(g_bn_a[ch + 0] * v.x + g_bn_b[ch + 0], 0.f);    \
                v.y = fmaxf(g_bn_a[ch + 1] * v.y + g_bn_b[ch + 1], 0.f);    \
                v.z = fmaxf(g_bn_a[ch + 2] * v.z + g_bn_b[ch + 2], 0.f);    \
                v.w = fmaxf(g_bn_a[ch + 3] * v.w + g_bn_b[ch + 3], 0.f);    \
            }                                                               \
            unsigned lo0, lo1;                                              \
            unsigned hi0 = packsplit(v.x, v.y, &lo0);                       \
            unsigned hi1 = packsplit(v.z, v.w, &lo1);                       \
            int o = lr[i] * P_STRIDE + lc4[i] * 2;                          \
            (BUF)[o] = hi0; (BUF)[o + 1] = hi1;                             \
            (BUF)[o + 128 * P_STRIDE] = lo0;                                \
            (BUF)[o + 128 * P_STRIDE + 1] = lo1;                            \
        }                                                                   \
    } while (0)

#define MMA16(A0, A1, A2, A3, B0, B1, C)                                \
    asm volatile(                                                       \
        "mma.sync.aligned.m16n8k16.row.col.f32.bf16.bf16.f32 "          \
        "{%0,%1,%2,%3}, {%4,%5,%6,%7}, {%8,%9}, {%0,%1,%2,%3};"         \
        : "+f"(C[0]), "+f"(C[1]), "+f"(C[2]), "+f"(C[3])                \
        : "r"(A0), "r"(A1), "r"(A2), "r"(A3), "r"(B0), "r"(B1))

    // prologue: tile b into buf 0
    {
        float4 pf[8];
        LOADX(b, pf);
        STOREX(Xb, pf);
    }
    __syncthreads();

    int nt = 0;
    for (int tile = b; tile < GEMM_TILES; tile += GEMM_BLK, nt++) {
        int cur = nt & 1;
        unsigned* Xh2 = Xb + cur * XBUF;
        unsigned* Xl2 = Xh2 + 128 * P_STRIDE;
        int row0 = tile * 128;
        int next = tile + GEMM_BLK;

        float4 pf[8];
        if (next < GEMM_TILES) LOADX(next, pf);

        float acc[2][4][4];
#pragma unroll
        for (int mi = 0; mi < 2; mi++)
#pragma unroll
            for (int ni = 0; ni < 4; ni++)
#pragma unroll
                for (int j = 0; j < 4; j++) acc[mi][ni][j] = 0.f;

#pragma unroll
        for (int kp = 0; kp < 64; kp += 8) {
            unsigned ah[2][4], al[2][4];
#pragma unroll
            for (int mi = 0; mi < 2; mi++) {
                int rb = mwid * 32 + mi * 16;
                int o0 = (rb + g) * P_STRIDE + kp + tg;
                int o1 = (rb + g + 8) * P_STRIDE + kp + tg;
                ah[mi][0] = Xh2[o0];
                ah[mi][1] = Xh2[o1];
                ah[mi][2] = Xh2[o0 + 4];
                ah[mi][3] = Xh2[o1 + 4];
                al[mi][0] = Xl2[o0];
                al[mi][1] = Xl2[o1];
                al[mi][2] = Xl2[o0 + 4];
                al[mi][3] = Xl2[o1 + 4];
            }
#pragma unroll
            for (int ni = 0; ni < 4; ni++) {
                int cb = nwid * 32 + ni * 8;
                int o = (cb + g) * P_STRIDE + kp + tg;
                unsigned bh0 = Wh2[o];
                unsigned bh1 = Wh2[o + 4];
                unsigned bl0 = Wl2[o];
                unsigned bl1 = Wl2[o + 4];
#pragma unroll
                for (int mi = 0; mi < 2; mi++) {
                    MMA16(ah[mi][0], ah[mi][1], ah[mi][2], ah[mi][3],
                          bh0, bh1, acc[mi][ni]);
                    MMA16(ah[mi][0], ah[mi][1], ah[mi][2], ah[mi][3],
                          bl0, bl1, acc[mi][ni]);
                    MMA16(al[mi][0], al[mi][1], al[mi][2], al[mi][3],
                          bh0, bh1, acc[mi][ni]);
                }
            }
        }

        if (next < GEMM_TILES) STOREX(Xb + (cur ^ 1) * XBUF, pf);

        // epilogue: fp16 pairs
#pragma unroll
        for (int mi = 0; mi < 2; mi++) {
#pragma unroll
            for (int ni = 0; ni < 4; ni++) {
                int col = nwid * 32 + ni * 8 + tg * 2;
                int r1 = row0 + mwid * 32 + mi * 16 + g;
                int r2 = r1 + 8;
                if (r1 < NN) {
                    __half2 h = __floats2half2_rn(acc[mi][ni][0], acc[mi][ni][1]);
                    g_h16u[(size_t)r1 * 64 + (col >> 1)] = *(unsigned*)&h;
                }
                if (r2 < NN) {
                    __half2 h = __floats2half2_rn(acc[mi][ni][2], acc[mi][ni][3]);
                    g_h16u[(size_t)r2 * 64 + (col >> 1)] = *(unsigned*)&h;
                }
            }
        }
        __syncthreads();
    }
#undef MMA16
#undef LOADX
#undef STOREX
}

// ---------------- aggregation (fp16 gather) + fused BN partial stats --------
__global__ void __launch_bounds__(256) k_agg(const float* __restrict__ bias) {
    __shared__ float ps[8][HH];
    __shared__ float pq[8][HH];
    int w = threadIdx.x >> 5;
    int lane = threadIdx.x & 31;
    int d = blockIdx.x * 8 + w;   // NN = 6250*8 exact

    const uint2* Hv = (const uint2*)g_h16u;
    float sd = g_dis[d];
    float ws = sd * sd;
    uint2 u = Hv[(size_t)d * 32 + lane];
    float2 f0 = __half22float2(*(__half2*)&u.x);
    float2 f1 = __half22float2(*(__half2*)&u.y);
    float4 acc = make_float4(f0.x * ws, f0.y * ws, f1.x * ws, f1.y * ws);

    int beg = g_ptr[d], end = g_ptr[d + 1];
    int j = beg;
    for (; j + 4 <= end; j += 4) {
        uint2 e0 = g_csr[j + 0], e1 = g_csr[j + 1];
        uint2 e2 = g_csr[j + 2], e3 = g_csr[j + 3];
        float w0 = __uint_as_float(e0.y), w1 = __uint_as_float(e1.y);
        float w2 = __uint_as_float(e2.y), w3 = __uint_as_float(e3.y);
        uint2 u0 = Hv[(size_t)e0.x * 32 + lane];
        uint2 u1 = Hv[(size_t)e1.x * 32 + lane];
        uint2 u2 = Hv[(size_t)e2.x * 32 + lane];
        uint2 u3 = Hv[(size_t)e3.x * 32 + lane];
        float2 a0, c0;
        a0 = __half22float2(*(__half2*)&u0.x); c0 = __half22float2(*(__half2*)&u0.y);
        acc.x += a0.x * w0; acc.y += a0.y * w0; acc.z += c0.x * w0; acc.w += c0.y * w0;
        a0 = __half22float2(*(__half2*)&u1.x); c0 = __half22float2(*(__half2*)&u1.y);
        acc.x += a0.x * w1; acc.y += a0.y * w1; acc.z += c0.x * w1; acc.w += c0.y * w1;
        a0 = __half22float2(*(__half2*)&u2.x); c0 = __half22float2(*(__half2*)&u2.y);
        acc.x += a0.x * w2; acc.y += a0.y * w2; acc.z += c0.x * w2; acc.w += c0.y * w2;
        a0 = __half22float2(*(__half2*)&u3.x); c0 = __half22float2(*(__half2*)&u3.y);
        acc.x += a0.x * w3; acc.y += a0.y * w3; acc.z += c0.x * w3; acc.w += c0.y * w3;
    }
    for (; j < end; j++) {
        uint2 e = g_csr[j];
        float wj = __uint_as_float(e.y);
        uint2 us = Hv[(size_t)e.x * 32 + lane];
        float2 a0 = __half22float2(*(__half2*)&us.x);
        float2 c0 = __half22float2(*(__half2*)&us.y);
        acc.x += a0.x * wj; acc.y += a0.y * wj; acc.z += c0.x * wj; acc.w += c0.y * wj;
    }
    float4 b4 = ((const float4*)bias)[lane];
    acc.x += b4.x; acc.y += b4.y; acc.z += b4.z; acc.w += b4.w;
    ((float4*)(g_agg + (size_t)d * HH))[lane] = acc;

    int c0i = 4 * lane;
    ps[w][c0i + 0] = acc.x; ps[w][c0i + 1] = acc.y;
    ps[w][c0i + 2] = acc.z; ps[w][c0i + 3] = acc.w;
    pq[w][c0i + 0] = acc.x * acc.x; pq[w][c0i + 1] = acc.y * acc.y;
    pq[w][c0i + 2] = acc.z * acc.z; pq[w][c0i + 3] = acc.w * acc.w;
    __syncthreads();
    int t = threadIdx.x;
    if (t < HH) {
        float s = 0.f;
#pragma unroll
        for (int i = 0; i < 8; i++) s += ps[i][t];
        g_ps1[blockIdx.x * HH + t] = s;
    } else {
        int c = t - HH;
        float s = 0.f;
#pragma unroll
        for (int i = 0; i < 8; i++) s += pq[i][c];
        g_pq1[blockIdx.x * HH + c] = s;
    }
}

// ---------------- BN stats: one launch (mid + ticketed final, race-free) ----
__global__ void __launch_bounds__(256) k_stats(int which,
                                               const float* __restrict__ gam,
                                               const float* __restrict__ bet) {
    __shared__ int islast;
    int b = blockIdx.x;
    int t = threadIdx.x;
    int c = t & (HH - 1);
    int isq = t >> 7;
    const float* src = isq ? g_pq1 : g_ps1;
    float s = 0.f;
    int r0 = b * ROWS_PER_STAT;
    int r1 = r0 + ROWS_PER_STAT;
    if (r1 > AGG_NB) r1 = AGG_NB;
    for (int r = r0; r < r1; r++) s += src[r * HH + c];
    if (isq) g_midq[b * HH + c] = s;
    else     g_mids[b * HH + c] = s;
    // ensure ALL threads' mid stores are done before taking the ticket
    __syncthreads();
    if (t == 0) {
        __threadfence();
        islast = (atomicAdd(&g_tick2[which], 1) == STAT_NB - 1);
    }
    __syncthreads();
    if (!islast) return;
    __threadfence();
    if (t < HH) {
        float su = 0.f, q = 0.f;
        for (int b2 = 0; b2 < STAT_NB; b2++) {
            su += g_mids[b2 * HH + t];
            q  += g_midq[b2 * HH + t];
        }
        float m = su / (float)NN;
        float var = q / (float)NN - m * m;
        float a = gam[t] * rsqrtf(var + EPSBN);
        g_bn_a[t] = a;
        g_bn_b[t] = bet[t] - m * a;
    }
}

// ---- pool (BN3+ReLU fused) + FC1 + ticketed head (fcBN + fc2) --------------
__global__ void __launch_bounds__(128) k_poolhead(
    const float* __restrict__ Wf, const float* __restrict__ bf,
    const float* __restrict__ gam, const float* __restrict__ bet,
    const float* __restrict__ W2f, const float* __restrict__ b2f,
    float* __restrict__ out) {
    __shared__ float pooled[HH];
    __shared__ float fa[FC1], fb[FC1];
    __shared__ int s_tk;
    int gI = blockIdx.x;
    int t = threadIdx.x;
    int beg = g_goff[gI], end = g_goff[gI + 1];
    float a = g_bn_a[t], b = g_bn_b[t];
    float acc = 0.f;
    for (int r = beg; r < end; r++) {
        float v = g_agg[(size_t)r * HH + t];
        acc += fmaxf(a * v + b, 0.f);
    }
    float cnt = (float)(end - beg);
    pooled[t] = acc / fmaxf(cnt, 1.f);
    __syncthreads();
    if (t < FC1) {
        float s = bf[t];
#pragma unroll 8
        for (int k = 0; k < HH; k++) s += pooled[k] * Wf[k * FC1 + t];
        g_z[gI * FC1 + t] = s;
    }
    __syncthreads();
    if (t == 0) {
        __threadfence();
        s_tk = atomicAdd(&g_tickP, 1);
    }
    __syncthreads();
    if (s_tk != GG - 1) return;       // last block runs the head
    __threadfence();
    if (t < FC1) {
        float s = 0.f, q = 0.f;
#pragma unroll 4
        for (int r = 0; r < GG; r++) {
            float v = g_z[r * FC1 + t];
            s += v;
            q += v * v;
        }
        float m = s / (float)GG;
        float var = q / (float)GG - m * m;
        float av = gam[t] * rsqrtf(var + EPSBN);
        fa[t] = av;
        fb[t] = bet[t] - m * av;
    }
    __syncthreads();
    for (int gg = t; gg < GG; gg += 128) {
        float s = b2f[0];
#pragma unroll 8
        for (int c = 0; c < FC1; c++) {
            float v = g_z[gg * FC1 + c];
            v = fmaxf(fa[c] * v + fb[c], 0.f);
            s += v * W2f[c];
        }
        out[gg] = s;
    }
}

// ---------------- launch ----------------
extern "C" void kernel_launch(void* const* d_in, const int* in_sizes, int n_in,
                              void* d_out, int out_size) {
    const float* x    = (const float*)d_in[0];
    const void*  eidx = d_in[1];
    const void*  batc = d_in[2];
    const float* W1 = (const float*)d_in[3];
    const float* b1 = (const float*)d_in[4];
    const float* g1 = (const float*)d_in[5];
    const float* be1 = (const float*)d_in[6];
    const float* W2 = (const float*)d_in[7];
    const float* b2 = (const float*)d_in[8];
    const float* g2 = (const float*)d_in[9];
    const float* be2 = (const float*)d_in[10];
    const float* W3 = (const float*)d_in[11];
    const float* b3 = (const float*)d_in[12];
    const float* g3 = (const float*)d_in[13];
    const float* be3 = (const float*)d_in[14];
    const float* fcW1 = (const float*)d_in[15];
    const float* fcb1 = (const float*)d_in[16];
    const float* fcg1 = (const float*)d_in[17];
    const float* fcbe1 = (const float*)d_in[18];
    const float* fcW2 = (const float*)d_in[19];
    const float* fcb2 = (const float*)d_in[20];
    float* out = (float*)d_out;

    float* pagg = nullptr;
    unsigned *pwth = nullptr, *pwtl = nullptr;
    cudaGetSymbolAddress((void**)&pagg, g_agg);
    cudaGetSymbolAddress((void**)&pwth, g_wt2h);
    cudaGetSymbolAddress((void**)&pwtl, g_wt2l);

    const int TB = 256;
    const int WSZ = HH * (HH / 2);   // uints per layer in g_wt2h/l

    static int init_done = 0;
    static cudaStream_t s2;
    static cudaEvent_t ev1, ev2;
    if (!init_done) {
        cudaFuncSetAttribute(k_gemm_tc<false>,
                             cudaFuncAttributeMaxDynamicSharedMemorySize, GEMM_SMEM);
        cudaFuncSetAttribute(k_gemm_tc<true>,
                             cudaFuncAttributeMaxDynamicSharedMemorySize, GEMM_SMEM);
        cudaStreamCreateWithFlags(&s2, cudaStreamNonBlocking);
        cudaEventCreateWithFlags(&ev1, cudaEventDisableTiming);
        cudaEventCreateWithFlags(&ev2, cudaEventDisableTiming);
        init_done = 1;
    }

    // preprocessing chain; layer-1 GEMM forked onto s2 (needs only pre1 + x)
    k_pre1<<<SCAN_NB, TB>>>(eidx, W1, W2, W3);
    cudaEventRecord(ev1, 0);
    cudaStreamWaitEvent(s2, ev1, 0);
    k_gemm_tc<false><<<GEMM_BLK, 512, GEMM_SMEM, s2>>>(x, pwth, pwtl);
    cudaEventRecord(ev2, s2);

    k_count<<<(EE + TB - 1) / TB, TB>>>(eidx, batc);
    k_scanall<<<SCAN_NB, SCAN_TB>>>();
    k_fill<<<(EE + TB - 1) / TB, TB>>>(eidx);
    cudaStreamWaitEvent(0, ev2, 0);

    // layer 1
    k_agg<<<AGG_NB, TB>>>(b1);
    k_stats<<<STAT_NB, TB>>>(0, g1, be1);
    // layer 2
    k_gemm_tc<true><<<GEMM_BLK, 512, GEMM_SMEM>>>(pagg, pwth + WSZ, pwtl + WSZ);
    k_agg<<<AGG_NB, TB>>>(b2);
    k_stats<<<STAT_NB, TB>>>(1, g2, be2);
    // layer 3
    k_gemm_tc<true><<<GEMM_BLK, 512, GEMM_SMEM>>>(pagg, pwth + 2 * WSZ, pwtl + 2 * WSZ);
    k_agg<<<AGG_NB, TB>>>(b3);
    k_stats<<<STAT_NB, TB>>>(2, g3, be3);

    // pool + fc1 + head, one kernel
    k_poolhead<<<GG, 128>>>(fcW1, fcb1, fcg1, fcbe1, fcW2, fcb2, out);
}